// round 1
// baseline (speedup 1.0000x reference)
#include <cuda_runtime.h>
#include <cuda_bf16.h>

#define NROWS  8192
#define DIM    1024
#define NPAIRS 1024
#define MARGIN_RANK 0.05f

// ---------------- device scratch (no allocations allowed) ----------------
__device__ float g_sp[NROWS];     // sim_pos per row
__device__ float g_sn[NROWS];     // sim_neg per row
__device__ float g_ssp[NROWS];    // bucket-sorted sim_pos
__device__ float g_ssn[NROWS];    // bucket-sorted sim_neg
__device__ int   g_slev[NROWS];   // bucket-sorted levels
__device__ int   g_bcount[NPAIRS];
__device__ int   g_bstart[NPAIRS];
__device__ int   g_bfill[NPAIRS];
__device__ float g_inv_tp, g_inv_tn;
__device__ float g_cons_sum, g_pos_sum, g_neg_sum;
__device__ int   g_cons_cnt, g_rank_cnt;

// ---------------- k0: zero counters + text-vector inverse norms ----------
__global__ void k0_init(const float* __restrict__ tp, const float* __restrict__ tn) {
    int t = threadIdx.x;                  // exactly DIM = NPAIRS = 1024 threads
    g_bcount[t] = 0;
    if (t == 0) {
        g_cons_sum = 0.f; g_pos_sum = 0.f; g_neg_sum = 0.f;
        g_cons_cnt = 0;   g_rank_cnt = 0;
    }
    float a = tp[t], b = tn[t];
    float pa = a * a, pb = b * b;
    __shared__ float sA[32], sB[32];
    #pragma unroll
    for (int o = 16; o; o >>= 1) {
        pa += __shfl_xor_sync(0xFFFFFFFFu, pa, o);
        pb += __shfl_xor_sync(0xFFFFFFFFu, pb, o);
    }
    int w = t >> 5, l = t & 31;
    if (l == 0) { sA[w] = pa; sB[w] = pb; }
    __syncthreads();
    if (w == 0) {
        pa = sA[l]; pb = sB[l];
        #pragma unroll
        for (int o = 16; o; o >>= 1) {
            pa += __shfl_xor_sync(0xFFFFFFFFu, pa, o);
            pb += __shfl_xor_sync(0xFFFFFFFFu, pb, o);
        }
        if (l == 0) { g_inv_tp = rsqrtf(pa); g_inv_tn = rsqrtf(pb); }
    }
}

// ---------------- k1: fused row-norm + 2x GEMV + pair histogram ----------
// One warp per row; 8 float4 per lane covers D=1024.
__global__ void __launch_bounds__(256) k1_gemv(
    const float4* __restrict__ x, const float4* __restrict__ tp4,
    const float4* __restrict__ tn4, const int* __restrict__ pair)
{
    int warp = (blockIdx.x * blockDim.x + threadIdx.x) >> 5;  // row id
    int lane = threadIdx.x & 31;
    const float4* row = x + (size_t)warp * (DIM / 4);

    float dp = 0.f, dn = 0.f, dx = 0.f;
    #pragma unroll
    for (int k = 0; k < 8; k++) {
        int j = k * 32 + lane;
        float4 v = row[j];
        float4 p = tp4[j];
        float4 q = tn4[j];
        dp += v.x*p.x + v.y*p.y + v.z*p.z + v.w*p.w;
        dn += v.x*q.x + v.y*q.y + v.z*q.z + v.w*q.w;
        dx += v.x*v.x + v.y*v.y + v.z*v.z + v.w*v.w;
    }
    #pragma unroll
    for (int o = 16; o; o >>= 1) {
        dp += __shfl_xor_sync(0xFFFFFFFFu, dp, o);
        dn += __shfl_xor_sync(0xFFFFFFFFu, dn, o);
        dx += __shfl_xor_sync(0xFFFFFFFFu, dx, o);
    }
    if (lane == 0) {
        float inv = rsqrtf(dx);
        g_sp[warp] = dp * inv * g_inv_tp;
        g_sn[warp] = dn * inv * g_inv_tn;
        atomicAdd(&g_bcount[pair[warp]], 1);
    }
}

// ---------------- k2: exclusive prefix scan over 1024 bucket counts -----
__global__ void k2_scan() {
    __shared__ int s[NPAIRS];
    int t = threadIdx.x;
    int c = g_bcount[t];
    s[t] = c;
    __syncthreads();
    for (int o = 1; o < NPAIRS; o <<= 1) {
        int v = (t >= o) ? s[t - o] : 0;
        __syncthreads();
        s[t] += v;
        __syncthreads();
    }
    int start = s[t] - c;
    g_bstart[t] = start;
    g_bfill[t]  = start;
}

// ---------------- k3: scatter rows into buckets --------------------------
__global__ void k3_scatter(const int* __restrict__ pair, const int* __restrict__ lev) {
    int i = blockIdx.x * blockDim.x + threadIdx.x;
    if (i >= NROWS) return;
    int pos = atomicAdd(&g_bfill[pair[i]], 1);
    g_ssp[pos]  = g_sp[i];
    g_ssn[pos]  = g_sn[i];
    g_slev[pos] = lev[i];
}

// ---------------- k4: per-bucket all-pairs loss terms --------------------
// One warp per bucket. Order within a bucket is arbitrary and irrelevant:
//   cons: unordered equal-level pair counted once (a<b);  |diff| symmetric.
//   rank: ordered condition lev_a < lev_b, scanned over the full rectangle.
__global__ void __launch_bounds__(256) k4_pairs() {
    int wg   = (blockIdx.x * blockDim.x + threadIdx.x) >> 5;  // bucket id
    int lane = threadIdx.x & 31;
    int start = g_bstart[wg];
    int c     = g_bcount[wg];

    float cs = 0.f, ps = 0.f, ns = 0.f;
    int cc = 0, rc = 0;

    for (int a = lane; a < c; a += 32) {
        float spa = g_ssp[start + a];
        float sna = g_ssn[start + a];
        int   la  = g_slev[start + a];
        for (int b = 0; b < c; b++) {
            int   lb  = g_slev[start + b];   // broadcast across warp (L1)
            float spb = g_ssp[start + b];
            float snb = g_ssn[start + b];
            if (la == lb && a < b) {
                cs += fabsf(spa - spb) + fabsf(sna - snb);
                cc++;
            }
            if (la < lb) {
                ps += fmaxf(MARGIN_RANK - (spa - spb), 0.f);
                ns += fmaxf(MARGIN_RANK + (sna - snb), 0.f);
                rc++;
            }
        }
    }
    #pragma unroll
    for (int o = 16; o; o >>= 1) {
        cs += __shfl_xor_sync(0xFFFFFFFFu, cs, o);
        ps += __shfl_xor_sync(0xFFFFFFFFu, ps, o);
        ns += __shfl_xor_sync(0xFFFFFFFFu, ns, o);
        cc += __shfl_xor_sync(0xFFFFFFFFu, cc, o);
        rc += __shfl_xor_sync(0xFFFFFFFFu, rc, o);
    }
    if (lane == 0 && (cc | rc)) {
        atomicAdd(&g_cons_sum, cs);
        atomicAdd(&g_pos_sum,  ps);
        atomicAdd(&g_neg_sum,  ns);
        atomicAdd(&g_cons_cnt, cc);
        atomicAdd(&g_rank_cnt, rc);
    }
}

// ---------------- k5: combine scalar --------------------------------------
__global__ void k5_final(float* __restrict__ out) {
    float lc = (g_cons_cnt > 0) ? g_cons_sum / (float)(2 * g_cons_cnt) : 0.f;
    float lp = (g_rank_cnt > 0) ? g_pos_sum  / (float)g_rank_cnt       : 0.f;
    float ln = (g_rank_cnt > 0) ? g_neg_sum  / (float)g_rank_cnt       : 0.f;
    out[0] = lc + lp + ln;
}

// ---------------- launch ---------------------------------------------------
extern "C" void kernel_launch(void* const* d_in, const int* in_sizes, int n_in,
                              void* d_out, int out_size) {
    const float* img  = (const float*)d_in[0];  // [8192, 1024]
    const float* tp   = (const float*)d_in[1];  // [1024]
    const float* tn   = (const float*)d_in[2];  // [1024]
    const int*   lev  = (const int*)  d_in[3];  // [8192]
    const int*   pair = (const int*)  d_in[4];  // [8192]
    float* out = (float*)d_out;

    k0_init<<<1, NPAIRS>>>(tp, tn);
    k1_gemv<<<(NROWS * 32) / 256, 256>>>(
        (const float4*)img, (const float4*)tp, (const float4*)tn, pair);
    k2_scan<<<1, NPAIRS>>>();
    k3_scatter<<<NROWS / 256, 256>>>(pair, lev);
    k4_pairs<<<NPAIRS / 8, 256>>>();
    k5_final<<<1, 1>>>(out);
}

// round 2
// speedup vs baseline: 1.0071x; 1.0071x over previous
#include <cuda_runtime.h>
#include <cuda_bf16.h>

#define NROWS  8192
#define DIM    1024
#define NPAIRS 1024
#define MARGIN_RANK 0.05f

// ---------------- device scratch (no allocations allowed) ----------------
__device__ float  g_sp[NROWS];      // dp * rsqrt(|row|^2)   (text norm NOT applied)
__device__ float  g_sn[NROWS];      // dn * rsqrt(|row|^2)
__device__ int    g_pos[NROWS];     // destination slot in bucket-sorted order
__device__ float4 g_sorted[NROWS];  // {sim_pos, sim_neg, lev_bits, 0} bucket-sorted
__device__ int    g_bcount[NPAIRS];
__device__ int    g_bstart[NPAIRS];
__device__ float  g_inv_tp, g_inv_tn;
__device__ float  g_cons_sum, g_pos_sum, g_neg_sum;
__device__ int    g_cons_cnt, g_rank_cnt;
__device__ int    g_done;

// ---------------- kA: row-norm + 2x GEMV (pure HBM stream) ---------------
// One warp per row, text vectors staged in shared, MLP=8 via explicit preload.
__global__ void __launch_bounds__(256) kA_gemv(
    const float4* __restrict__ x, const float4* __restrict__ tp4,
    const float4* __restrict__ tn4)
{
    __shared__ float4 stp[DIM / 4], stn[DIM / 4];
    int t = threadIdx.x;
    stp[t] = tp4[t];
    stn[t] = tn4[t];
    __syncthreads();

    int warp = (blockIdx.x * 256 + t) >> 5;   // row id
    int lane = t & 31;
    const float4* row = x + (size_t)warp * (DIM / 4);

    float4 v[8];
    #pragma unroll
    for (int k = 0; k < 8; k++) v[k] = row[k * 32 + lane];   // 8 outstanding loads

    float dp = 0.f, dn = 0.f, dx = 0.f;
    #pragma unroll
    for (int k = 0; k < 8; k++) {
        float4 p = stp[k * 32 + lane];
        float4 q = stn[k * 32 + lane];
        dp += v[k].x*p.x + v[k].y*p.y + v[k].z*p.z + v[k].w*p.w;
        dn += v[k].x*q.x + v[k].y*q.y + v[k].z*q.z + v[k].w*q.w;
        dx += v[k].x*v[k].x + v[k].y*v[k].y + v[k].z*v[k].z + v[k].w*v[k].w;
    }
    #pragma unroll
    for (int o = 16; o; o >>= 1) {
        dp += __shfl_xor_sync(0xFFFFFFFFu, dp, o);
        dn += __shfl_xor_sync(0xFFFFFFFFu, dn, o);
        dx += __shfl_xor_sync(0xFFFFFFFFu, dx, o);
    }
    if (lane == 0) {
        float inv = rsqrtf(dx);
        g_sp[warp] = dp * inv;
        g_sn[warp] = dn * inv;
    }
}

// ---------------- kB: one block does everything scalar --------------------
// zero accumulators, text norms, histogram (shared atomic rank), scan, positions.
__global__ void kB_prep(const float* __restrict__ tp, const float* __restrict__ tn,
                        const int* __restrict__ pair)
{
    __shared__ int scnt[NPAIRS];   // histogram counts
    __shared__ int s[NPAIRS];      // scan workspace
    __shared__ int sstart[NPAIRS]; // exclusive starts
    __shared__ float sA[32], sB[32];

    int t = threadIdx.x;           // 1024 threads
    scnt[t] = 0;
    if (t == 0) {
        g_cons_sum = 0.f; g_pos_sum = 0.f; g_neg_sum = 0.f;
        g_cons_cnt = 0;   g_rank_cnt = 0;  g_done = 0;
    }

    // text-vector inverse norms (t spans DIM exactly)
    float a = tp[t], b = tn[t];
    float pa = a * a, pb = b * b;
    #pragma unroll
    for (int o = 16; o; o >>= 1) {
        pa += __shfl_xor_sync(0xFFFFFFFFu, pa, o);
        pb += __shfl_xor_sync(0xFFFFFFFFu, pb, o);
    }
    int w = t >> 5, l = t & 31;
    if (l == 0) { sA[w] = pa; sB[w] = pb; }
    __syncthreads();
    if (w == 0) {
        pa = sA[l]; pb = sB[l];
        #pragma unroll
        for (int o = 16; o; o >>= 1) {
            pa += __shfl_xor_sync(0xFFFFFFFFu, pa, o);
            pb += __shfl_xor_sync(0xFFFFFFFFu, pb, o);
        }
        if (l == 0) { g_inv_tp = rsqrtf(pa); g_inv_tn = rsqrtf(pb); }
    }
    __syncthreads();

    // histogram with rank capture (shared atomics, ~8-way contention)
    int myp[8], myr[8];
    #pragma unroll
    for (int k = 0; k < 8; k++) {
        int i = t + k * NPAIRS;
        int p = pair[i];
        myp[k] = p;
        myr[k] = atomicAdd(&scnt[p], 1);
    }
    __syncthreads();

    // inclusive Hillis–Steele scan -> exclusive starts
    int c = scnt[t];
    s[t] = c;
    __syncthreads();
    for (int o = 1; o < NPAIRS; o <<= 1) {
        int v = (t >= o) ? s[t - o] : 0;
        __syncthreads();
        s[t] += v;
        __syncthreads();
    }
    int start = s[t] - c;
    sstart[t]   = start;
    g_bstart[t] = start;
    g_bcount[t] = c;
    __syncthreads();

    // final coalesced positions
    #pragma unroll
    for (int k = 0; k < 8; k++)
        g_pos[t + k * NPAIRS] = sstart[myp[k]] + myr[k];
}

// ---------------- kC: atomic-free scatter into packed float4 -------------
__global__ void __launch_bounds__(256) kC_scatter(const int* __restrict__ lev) {
    int i = blockIdx.x * 256 + threadIdx.x;
    float4 v;
    v.x = g_sp[i] * g_inv_tp;
    v.y = g_sn[i] * g_inv_tn;
    v.z = __int_as_float(lev[i]);
    v.w = 0.f;
    g_sorted[g_pos[i]] = v;
}

// ---------------- kD: per-bucket all-pairs + fused finalize ---------------
__global__ void __launch_bounds__(256) kD_pairs(float* __restrict__ out) {
    int wg   = (blockIdx.x * 256 + threadIdx.x) >> 5;  // bucket id
    int lane = threadIdx.x & 31;
    int start = g_bstart[wg];
    int c     = g_bcount[wg];

    float cs = 0.f, ps = 0.f, ns = 0.f;
    int cc = 0, rc = 0;

    for (int a = lane; a < c; a += 32) {
        float4 va = g_sorted[start + a];
        int la = __float_as_int(va.z);
        for (int b = 0; b < c; b++) {
            float4 vb = g_sorted[start + b];   // warp-broadcast load
            int lb = __float_as_int(vb.z);
            if (la == lb && a < b) {
                cs += fabsf(va.x - vb.x) + fabsf(va.y - vb.y);
                cc++;
            }
            if (la < lb) {
                ps += fmaxf(MARGIN_RANK - (va.x - vb.x), 0.f);
                ns += fmaxf(MARGIN_RANK + (va.y - vb.y), 0.f);
                rc++;
            }
        }
    }
    #pragma unroll
    for (int o = 16; o; o >>= 1) {
        cs += __shfl_xor_sync(0xFFFFFFFFu, cs, o);
        ps += __shfl_xor_sync(0xFFFFFFFFu, ps, o);
        ns += __shfl_xor_sync(0xFFFFFFFFu, ns, o);
        cc += __shfl_xor_sync(0xFFFFFFFFu, cc, o);
        rc += __shfl_xor_sync(0xFFFFFFFFu, rc, o);
    }
    if (lane == 0 && (cc | rc)) {
        atomicAdd(&g_cons_sum, cs);
        atomicAdd(&g_pos_sum,  ps);
        atomicAdd(&g_neg_sum,  ns);
        atomicAdd(&g_cons_cnt, cc);
        atomicAdd(&g_rank_cnt, rc);
    }

    // fused finalize: last block to arrive writes the scalar
    __syncthreads();
    if (threadIdx.x == 0) {
        __threadfence();
        if (atomicAdd(&g_done, 1) == (int)gridDim.x - 1) {
            __threadfence();
            float lc = (g_cons_cnt > 0) ? g_cons_sum / (float)(2 * g_cons_cnt) : 0.f;
            float lp = (g_rank_cnt > 0) ? g_pos_sum  / (float)g_rank_cnt       : 0.f;
            float ln = (g_rank_cnt > 0) ? g_neg_sum  / (float)g_rank_cnt       : 0.f;
            out[0] = lc + lp + ln;
        }
    }
}

// ---------------- launch ---------------------------------------------------
extern "C" void kernel_launch(void* const* d_in, const int* in_sizes, int n_in,
                              void* d_out, int out_size) {
    const float* img  = (const float*)d_in[0];  // [8192, 1024]
    const float* tp   = (const float*)d_in[1];  // [1024]
    const float* tn   = (const float*)d_in[2];  // [1024]
    const int*   lev  = (const int*)  d_in[3];  // [8192]
    const int*   pair = (const int*)  d_in[4];  // [8192]
    float* out = (float*)d_out;

    kA_gemv<<<(NROWS * 32) / 256, 256>>>(
        (const float4*)img, (const float4*)tp, (const float4*)tn);
    kB_prep<<<1, NPAIRS>>>(tp, tn, pair);
    kC_scatter<<<NROWS / 256, 256>>>(lev);
    kD_pairs<<<(NPAIRS * 32) / 256, 256>>>(out);
}